// round 13
// baseline (speedup 1.0000x reference)
#include <cuda_runtime.h>
#include <math.h>

#define FULL 0xFFFFFFFFu
#define T_LEN 2048
#define CHUNKS 16          // 16 chunks x 128 floats per row
#define WPB 8              // warps per block, 1 row per warp
#define STAGES 4           // cp.async pipeline depth (3 issued ahead)

__device__ __forceinline__ void cp_async16(void* smem_dst, const void* gmem_src) {
    unsigned s = (unsigned)__cvta_generic_to_shared(smem_dst);
    asm volatile("cp.async.cg.shared.global [%0], [%1], 16;\n" :: "r"(s), "l"(gmem_src));
}
#define CP_COMMIT() asm volatile("cp.async.commit_group;\n" ::)
#define CP_WAIT(n)  asm volatile("cp.async.wait_group %0;\n" :: "n"(n))

__global__ __launch_bounds__(256, 6)
void scpp_kernel(const float* __restrict__ event_times,
                 const float* __restrict__ input_mask,
                 const float* __restrict__ t0p,
                 const float* __restrict__ t1p,
                 const float* __restrict__ mup,
                 const float* __restrict__ betap,
                 float* __restrict__ out)
{
    const int lane = threadIdx.x & 31;
    const int w    = threadIdx.x >> 5;
    const int row  = blockIdx.x * WPB + w;

    const float mu   = log1pf(expf(__ldg(mup)));
    const float beta = log1pf(expf(__ldg(betap)));
    const float t0   = __ldg(t0p);
    const float t1   = __ldg(t1p);

    const float4* ev = reinterpret_cast<const float4*>(event_times + (size_t)row * T_LEN);
    const float4* mk = reinterpret_cast<const float4*>(input_mask  + (size_t)row * T_LEN);

    // [warp][stage][ev|mk][lane] : 8 * 4 * 2 * 32 * 16B = 32 KB
    __shared__ float4 buf[WPB][STAGES][2][32];

    // ---- prologue: stage chunks 0..2 into slots 0..2 (3 groups in flight) ----
    #pragma unroll
    for (int s = 0; s < STAGES - 1; s++) {
        cp_async16(&buf[w][s][0][lane], ev + 32 * s + lane);
        cp_async16(&buf[w][s][1][lane], mk + 32 * s + lane);
        CP_COMMIT();
    }

    float sumt = 0.f;     // sum mask * t
    float sumidx = 0.f;   // sum mask * index (integer-valued < 2^24: exact)
    float S = 0.f;        // sum masked exp(mu*t - beta*k)
    float T = 0.f;        // running masked count (warp-uniform)

    #pragma unroll 4
    for (int i = 0; i < CHUNKS; i++) {
        // chunk i (in slot i&3) is complete once <=2 groups remain outstanding
        CP_WAIT(STAGES - 2);
        const int slot = i & (STAGES - 1);
        const float4 e = buf[w][slot][0][lane];
        const float4 m = buf[w][slot][1][lane];

        // refill: chunk i+3 goes into slot (i+3)&3 — the slot it is READ from.
        // That slot last held chunk i-1, consumed at iteration i-1 (program order).
        if (i + STAGES - 1 < CHUNKS) {
            const int nslot = (i + STAGES - 1) & (STAGES - 1);
            cp_async16(&buf[w][nslot][0][lane], ev + 32 * (i + STAGES - 1) + lane);
            cp_async16(&buf[w][nslot][1][lane], mk + 32 * (i + STAGES - 1) + lane);
        }
        CP_COMMIT();   // empty group near the tail keeps wait counts consistent

        // ---- streaming sums (always) ----
        sumt = fmaf(m.x, e.x, sumt); sumt = fmaf(m.y, e.y, sumt);
        sumt = fmaf(m.z, e.z, sumt); sumt = fmaf(m.w, e.w, sumt);
        const float cnt  = (m.x + m.y) + (m.z + m.w);
        const float base = (float)(128 * i + 4 * lane);
        sumidx = fmaf(cnt, base, sumidx);
        sumidx += fmaf(3.f, m.w, fmaf(2.f, m.z, m.y));

        // ---- scan + gated exp, only while terms can be nonzero (warp-uniform) ----
        if (beta * T < 106.f) {
            float s = cnt;
            #pragma unroll
            for (int off = 1; off < 32; off <<= 1) {
                const float u = __shfl_up_sync(FULL, s, off);
                if (lane >= off) s += u;
            }
            if (beta * T < 104.f) {   // expf underflow bound
                float k = T + (s - cnt);
                if (m.x > 0.5f) { S += expf(fmaf(mu, e.x, -beta * k)); k += 1.f; }
                if (m.y > 0.5f) { S += expf(fmaf(mu, e.y, -beta * k)); k += 1.f; }
                if (m.z > 0.5f) { S += expf(fmaf(mu, e.z, -beta * k)); k += 1.f; }
                if (m.w > 0.5f) { S += expf(fmaf(mu, e.w, -beta * k)); }
            }
            T += __shfl_sync(FULL, s, 31);
        }
        // once beta*T >= 106: every remaining term AND the t1 tail are exact 0.0f
    }

    // ---- warp reductions ----
    #pragma unroll
    for (int off = 16; off; off >>= 1) {
        sumt   += __shfl_down_sync(FULL, sumt,   off);
        sumidx += __shfl_down_sync(FULL, sumidx, off);
        S      += __shfl_down_sync(FULL, S,      off);
    }

    if (lane == 0) {
        const float ll  = fmaf(mu, sumt, -beta * sumidx);
        const float emb = expf(-beta);
        // telescoped compensator: (1-e^{-b})*S - e^{mu*t0} + e^{mu*t1 - b*M}
        float comp = fmaf(1.f - emb, S, -expf(mu * t0));
        comp += expf(fmaf(mu, t1, -beta * T));   // exact 0 after underflow
        out[row] = ll - comp / mu;
    }
}

extern "C" void kernel_launch(void* const* d_in, const int* in_sizes, int n_in,
                              void* d_out, int out_size)
{
    const float* event_times = (const float*)d_in[0];
    // d_in[1] = spatial_locations : unused by the op
    const float* input_mask  = (const float*)d_in[2];
    const float* t0          = (const float*)d_in[3];
    const float* t1          = (const float*)d_in[4];
    const float* mu_param    = (const float*)d_in[5];
    const float* beta_param  = (const float*)d_in[6];
    float* out = (float*)d_out;

    const int n_rows = out_size;  // 8192
    scpp_kernel<<<n_rows / WPB, 256>>>(event_times, input_mask,
                                       t0, t1, mu_param, beta_param, out);
}

// round 14
// speedup vs baseline: 1.0643x; 1.0643x over previous
#include <cuda_runtime.h>
#include <math.h>

#define FULL 0xFFFFFFFFu
#define T_LEN 2048
#define NROWS 8192
#define QCHUNKS 4          // chunks per warp-unit (512 elems)
#define WPB 8              // warps per block -> block = 2 full rows

// per-quarter partials (deterministic scratch, no allocation)
__device__ float g_sumt[4][NROWS];
__device__ float g_sumidx[4][NROWS];
__device__ float g_S[NROWS];
__device__ float g_T[NROWS];

// streaming sums for one chunk (absolute element base = abase)
#define SUMS(e, m, abase)                                                 \
    do {                                                                  \
        sumt = fmaf((m).x, (e).x, sumt); sumt = fmaf((m).y, (e).y, sumt); \
        sumt = fmaf((m).z, (e).z, sumt); sumt = fmaf((m).w, (e).w, sumt); \
        const float cnt_ = ((m).x + (m).y) + ((m).z + (m).w);             \
        sumidx = fmaf(cnt_, (float)(abase), sumidx);                      \
        sumidx += fmaf(3.f, (m).w, fmaf(2.f, (m).z, (m).y));              \
    } while (0)

// gated scan + exp for one chunk; updates S, T (warp-uniform gate)
#define P1CHUNK(e, m)                                                     \
    do {                                                                  \
        if (beta * T < 106.f) {                                           \
            const float cnt = ((m).x + (m).y) + ((m).z + (m).w);          \
            float s = cnt;                                                \
            _Pragma("unroll")                                             \
            for (int off = 1; off < 32; off <<= 1) {                      \
                const float u = __shfl_up_sync(FULL, s, off);             \
                if (lane >= off) s += u;                                  \
            }                                                             \
            if (beta * T < 104.f) {                                       \
                float k = T + (s - cnt);                                  \
                if ((m).x > 0.5f) { S += expf(fmaf(mu, (e).x, -beta * k)); k += 1.f; } \
                if ((m).y > 0.5f) { S += expf(fmaf(mu, (e).y, -beta * k)); k += 1.f; } \
                if ((m).z > 0.5f) { S += expf(fmaf(mu, (e).z, -beta * k)); k += 1.f; } \
                if ((m).w > 0.5f) { S += expf(fmaf(mu, (e).w, -beta * k)); } \
            }                                                             \
            T += __shfl_sync(FULL, s, 31);                                \
        }                                                                 \
    } while (0)

__global__ __launch_bounds__(256, 4)
void scpp_partial(const float* __restrict__ event_times,
                  const float* __restrict__ input_mask,
                  const float* __restrict__ mup,
                  const float* __restrict__ betap)
{
    const int lane = threadIdx.x & 31;
    const int w    = threadIdx.x >> 5;
    const int unit = blockIdx.x * WPB + w;
    const int row  = unit >> 2;
    const int q    = unit & 3;

    const float mu   = log1pf(expf(__ldg(mup)));
    const float beta = log1pf(expf(__ldg(betap)));

    const float4* ev = reinterpret_cast<const float4*>(event_times + (size_t)row * T_LEN) + q * 128;
    const float4* mk = reinterpret_cast<const float4*>(input_mask  + (size_t)row * T_LEN) + q * 128;

    // front-batch all 8 loads: 4 chunks x (ev, mk) -> MLP 8
    const float4 e0 = ev[lane +  0], e1 = ev[lane + 32];
    const float4 e2 = ev[lane + 64], e3 = ev[lane + 96];
    const float4 m0 = mk[lane +  0], m1 = mk[lane + 32];
    const float4 m2 = mk[lane + 64], m3 = mk[lane + 96];

    float sumt = 0.f, sumidx = 0.f;
    const int abase0 = q * 512 + 4 * lane;

    SUMS(e0, m0, abase0 +   0);
    SUMS(e1, m1, abase0 + 128);
    SUMS(e2, m2, abase0 + 256);
    SUMS(e3, m3, abase0 + 384);

    float S = 0.f, T = 0.f;
    if (q == 0) {
        P1CHUNK(e0, m0);
        P1CHUNK(e1, m1);
        P1CHUNK(e2, m2);
        P1CHUNK(e3, m3);
        // rare fallback (arbitrary masks): continue scan+exp over chunks 4..15
        if (beta * T < 106.f) {
            const float4* evr = reinterpret_cast<const float4*>(event_times + (size_t)row * T_LEN);
            const float4* mkr = reinterpret_cast<const float4*>(input_mask  + (size_t)row * T_LEN);
            for (int i = 4; i < 16 && beta * T < 106.f; i++) {
                const float4 e = evr[lane + 32 * i];
                const float4 m = mkr[lane + 32 * i];
                P1CHUNK(e, m);
            }
        }
    }

    // warp reductions
    #pragma unroll
    for (int off = 16; off; off >>= 1) {
        sumt   += __shfl_down_sync(FULL, sumt,   off);
        sumidx += __shfl_down_sync(FULL, sumidx, off);
        S      += __shfl_down_sync(FULL, S,      off);
    }

    if (lane == 0) {
        g_sumt[q][row]   = sumt;
        g_sumidx[q][row] = sumidx;
        if (q == 0) { g_S[row] = S; g_T[row] = T; }
    }
}

__global__ __launch_bounds__(256)
void scpp_combine(const float* __restrict__ t0p,
                  const float* __restrict__ t1p,
                  const float* __restrict__ mup,
                  const float* __restrict__ betap,
                  float* __restrict__ out)
{
    const int row = blockIdx.x * 256 + threadIdx.x;
    if (row >= NROWS) return;

    const float mu   = log1pf(expf(__ldg(mup)));
    const float beta = log1pf(expf(__ldg(betap)));
    const float t0   = __ldg(t0p);
    const float t1   = __ldg(t1p);

    const float st = (g_sumt[0][row]   + g_sumt[1][row])   + (g_sumt[2][row]   + g_sumt[3][row]);
    const float si = (g_sumidx[0][row] + g_sumidx[1][row]) + (g_sumidx[2][row] + g_sumidx[3][row]);
    const float S  = g_S[row];
    const float T  = g_T[row];

    const float ll  = fmaf(mu, st, -beta * si);
    const float emb = expf(-beta);
    // telescoped compensator: (1-e^{-b})*S - e^{mu*t0} + e^{mu*t1 - b*M}
    float comp = fmaf(1.f - emb, S, -expf(mu * t0));
    comp += expf(fmaf(mu, t1, -beta * T));   // exact 0 after underflow
    out[row] = ll - comp / mu;
}

extern "C" void kernel_launch(void* const* d_in, const int* in_sizes, int n_in,
                              void* d_out, int out_size)
{
    const float* event_times = (const float*)d_in[0];
    // d_in[1] = spatial_locations : unused by the op
    const float* input_mask  = (const float*)d_in[2];
    const float* t0          = (const float*)d_in[3];
    const float* t1          = (const float*)d_in[4];
    const float* mu_param    = (const float*)d_in[5];
    const float* beta_param  = (const float*)d_in[6];
    float* out = (float*)d_out;

    const int n_units  = NROWS * 4;            // 32768 quarter-row units
    const int n_blocks = n_units / WPB;        // 4096
    scpp_partial<<<n_blocks, 256>>>(event_times, input_mask, mu_param, beta_param);
    scpp_combine<<<NROWS / 256, 256>>>(t0, t1, mu_param, beta_param, out);
}

// round 15
// speedup vs baseline: 1.1517x; 1.0822x over previous
#include <cuda_runtime.h>
#include <math.h>

#define FULL 0xFFFFFFFFu
#define T_LEN 2048
#define NROWS 8192
#define WPB 8              // warps per block; warps 0-3 = row 2b, warps 4-7 = row 2b+1

// streaming sums for one chunk (absolute element base = abase)
#define SUMS(e, m, abase)                                                 \
    do {                                                                  \
        sumt = fmaf((m).x, (e).x, sumt); sumt = fmaf((m).y, (e).y, sumt); \
        sumt = fmaf((m).z, (e).z, sumt); sumt = fmaf((m).w, (e).w, sumt); \
        const float cnt_ = ((m).x + (m).y) + ((m).z + (m).w);             \
        sumidx = fmaf(cnt_, (float)(abase), sumidx);                      \
        sumidx += fmaf(3.f, (m).w, fmaf(2.f, (m).z, (m).y));              \
    } while (0)

// gated scan + exp for one chunk; updates S, T (warp-uniform gate)
#define P1CHUNK(e, m)                                                     \
    do {                                                                  \
        if (beta * T < 106.f) {                                           \
            const float cnt = ((m).x + (m).y) + ((m).z + (m).w);          \
            float s = cnt;                                                \
            _Pragma("unroll")                                             \
            for (int off = 1; off < 32; off <<= 1) {                      \
                const float u = __shfl_up_sync(FULL, s, off);             \
                if (lane >= off) s += u;                                  \
            }                                                             \
            if (beta * T < 104.f) {                                       \
                float k = T + (s - cnt);                                  \
                if ((m).x > 0.5f) { S += expf(fmaf(mu, (e).x, -beta * k)); k += 1.f; } \
                if ((m).y > 0.5f) { S += expf(fmaf(mu, (e).y, -beta * k)); k += 1.f; } \
                if ((m).z > 0.5f) { S += expf(fmaf(mu, (e).z, -beta * k)); k += 1.f; } \
                if ((m).w > 0.5f) { S += expf(fmaf(mu, (e).w, -beta * k)); } \
            }                                                             \
            T += __shfl_sync(FULL, s, 31);                                \
        }                                                                 \
    } while (0)

__global__ __launch_bounds__(256, 4)
void scpp_kernel(const float* __restrict__ event_times,
                 const float* __restrict__ input_mask,
                 const float* __restrict__ t0p,
                 const float* __restrict__ t1p,
                 const float* __restrict__ mup,
                 const float* __restrict__ betap,
                 float* __restrict__ out)
{
    const int lane = threadIdx.x & 31;
    const int w    = threadIdx.x >> 5;
    const int unit = blockIdx.x * WPB + w;
    const int row  = unit >> 2;         // warps 0-3 -> row 2b, warps 4-7 -> row 2b+1
    const int q    = unit & 3;          // quarter index within the row

    const float mu   = log1pf(expf(__ldg(mup)));
    const float beta = log1pf(expf(__ldg(betap)));
    const float t0   = __ldg(t0p);
    const float t1   = __ldg(t1p);

    const float4* ev = reinterpret_cast<const float4*>(event_times + (size_t)row * T_LEN) + q * 128;
    const float4* mk = reinterpret_cast<const float4*>(input_mask  + (size_t)row * T_LEN) + q * 128;

    // front-batch all 8 loads: 4 chunks x (ev, mk) -> MLP 8
    const float4 e0 = ev[lane +  0], e1 = ev[lane + 32];
    const float4 e2 = ev[lane + 64], e3 = ev[lane + 96];
    const float4 m0 = mk[lane +  0], m1 = mk[lane + 32];
    const float4 m2 = mk[lane + 64], m3 = mk[lane + 96];

    float sumt = 0.f, sumidx = 0.f;
    const int abase0 = q * 512 + 4 * lane;

    SUMS(e0, m0, abase0 +   0);
    SUMS(e1, m1, abase0 + 128);
    SUMS(e2, m2, abase0 + 256);
    SUMS(e3, m3, abase0 + 384);

    float S = 0.f, T = 0.f;
    if (q == 0) {
        P1CHUNK(e0, m0);
        P1CHUNK(e1, m1);
        P1CHUNK(e2, m2);
        P1CHUNK(e3, m3);
        // rare fallback (arbitrary masks): continue scan+exp over chunks 4..15
        if (beta * T < 106.f) {
            const float4* evr = reinterpret_cast<const float4*>(event_times + (size_t)row * T_LEN);
            const float4* mkr = reinterpret_cast<const float4*>(input_mask  + (size_t)row * T_LEN);
            for (int i = 4; i < 16 && beta * T < 106.f; i++) {
                const float4 e = evr[lane + 32 * i];
                const float4 m = mkr[lane + 32 * i];
                P1CHUNK(e, m);
            }
        }
    }

    // ---- warp reductions ----
    #pragma unroll
    for (int off = 16; off; off >>= 1) {
        sumt   += __shfl_down_sync(FULL, sumt,   off);
        sumidx += __shfl_down_sync(FULL, sumidx, off);
        S      += __shfl_down_sync(FULL, S,      off);
    }

    // ---- in-block combine: 4 quarters of each row live in this block ----
    __shared__ float sm[WPB][4];   // sumt, sumidx, S, T per warp
    if (lane == 0) {
        sm[w][0] = sumt;
        sm[w][1] = sumidx;
        sm[w][2] = S;
        sm[w][3] = T;
    }
    __syncthreads();

    if (q == 0 && lane == 0) {
        // my row's quarters are warps w .. w+3
        const float st = (sm[w][0] + sm[w+1][0]) + (sm[w+2][0] + sm[w+3][0]);
        const float si = (sm[w][1] + sm[w+1][1]) + (sm[w+2][1] + sm[w+3][1]);
        const float Ss = sm[w][2];     // only q==0 produced S, T
        const float Tt = sm[w][3];

        const float ll  = fmaf(mu, st, -beta * si);
        const float emb = expf(-beta);
        // telescoped compensator: (1-e^{-b})*S - e^{mu*t0} + e^{mu*t1 - b*M}
        float comp = fmaf(1.f - emb, Ss, -expf(mu * t0));
        comp += expf(fmaf(mu, t1, -beta * Tt));   // exact 0 after underflow
        out[row] = ll - comp / mu;
    }
}

extern "C" void kernel_launch(void* const* d_in, const int* in_sizes, int n_in,
                              void* d_out, int out_size)
{
    const float* event_times = (const float*)d_in[0];
    // d_in[1] = spatial_locations : unused by the op
    const float* input_mask  = (const float*)d_in[2];
    const float* t0          = (const float*)d_in[3];
    const float* t1          = (const float*)d_in[4];
    const float* mu_param    = (const float*)d_in[5];
    const float* beta_param  = (const float*)d_in[6];
    float* out = (float*)d_out;

    const int n_units  = NROWS * 4;            // 32768 quarter-row units
    const int n_blocks = n_units / WPB;        // 4096
    scpp_kernel<<<n_blocks, 256>>>(event_times, input_mask,
                                   t0, t1, mu_param, beta_param, out);
}

// round 16
// speedup vs baseline: 1.1635x; 1.0102x over previous
#include <cuda_runtime.h>
#include <math.h>

#define FULL 0xFFFFFFFFu
#define T_LEN 2048
#define NROWS 8192
#define WPB 8              // warps/block; w0-3 = row 2b (q0..3), w4-7 = row 2b+1

// streaming sums for one chunk (absolute element base = abase)
#define SUMS(e, m, abase)                                                 \
    do {                                                                  \
        sumt = fmaf((m).x, (e).x, sumt); sumt = fmaf((m).y, (e).y, sumt); \
        sumt = fmaf((m).z, (e).z, sumt); sumt = fmaf((m).w, (e).w, sumt); \
        const float cnt_ = ((m).x + (m).y) + ((m).z + (m).w);             \
        sumidx = fmaf(cnt_, (float)(abase), sumidx);                      \
        sumidx += fmaf(3.f, (m).w, fmaf(2.f, (m).z, (m).y));              \
    } while (0)

// gated scan + exp for one chunk; updates S, T (warp-uniform gate)
#define P1CHUNK(e, m)                                                     \
    do {                                                                  \
        if (beta * T < 106.f) {                                           \
            const float cnt = ((m).x + (m).y) + ((m).z + (m).w);          \
            float s = cnt;                                                \
            _Pragma("unroll")                                             \
            for (int off = 1; off < 32; off <<= 1) {                      \
                const float u = __shfl_up_sync(FULL, s, off);             \
                if (lane >= off) s += u;                                  \
            }                                                             \
            if (beta * T < 104.f) {                                       \
                float k = T + (s - cnt);                                  \
                if ((m).x > 0.5f) { S += expf(fmaf(mu, (e).x, -beta * k)); k += 1.f; } \
                if ((m).y > 0.5f) { S += expf(fmaf(mu, (e).y, -beta * k)); k += 1.f; } \
                if ((m).z > 0.5f) { S += expf(fmaf(mu, (e).z, -beta * k)); k += 1.f; } \
                if ((m).w > 0.5f) { S += expf(fmaf(mu, (e).w, -beta * k)); } \
            }                                                             \
            T += __shfl_sync(FULL, s, 31);                                \
        }                                                                 \
    } while (0)

__global__ __launch_bounds__(256, 4)
void scpp_kernel(const float* __restrict__ event_times,
                 const float* __restrict__ input_mask,
                 const float* __restrict__ t0p,
                 const float* __restrict__ t1p,
                 const float* __restrict__ mup,
                 const float* __restrict__ betap,
                 float* __restrict__ out)
{
    const int lane = threadIdx.x & 31;
    const int w    = threadIdx.x >> 5;
    const int unit = blockIdx.x * WPB + w;
    const int row  = unit >> 2;
    const int q    = unit & 3;

    const float4* evr = reinterpret_cast<const float4*>(event_times + (size_t)row * T_LEN);
    const float4* mkr = reinterpret_cast<const float4*>(input_mask  + (size_t)row * T_LEN);

    float sumt = 0.f, sumidx = 0.f, S = 0.f, T = 0.f;
    float mu = 0.f, beta = 0.f, t0 = 0.f, t1 = 0.f;   // only q==0 populates

    __shared__ float sm[WPB][4];   // sumt, sumidx, S, T per warp

    if (q == 0) {
        // ---- chunks 0..2 + all scan/exp duty ----
        const float4 e0 = evr[lane +  0], e1 = evr[lane + 32], e2 = evr[lane + 64];
        const float4 m0 = mkr[lane +  0], m1 = mkr[lane + 32], m2 = mkr[lane + 64];

        // params load + softplus chains overlap the data loads above
        mu   = log1pf(expf(__ldg(mup)));
        beta = log1pf(expf(__ldg(betap)));
        t0   = __ldg(t0p);
        t1   = __ldg(t1p);

        const int ab = 4 * lane;
        SUMS(e0, m0, ab +   0);
        SUMS(e1, m1, ab + 128);
        SUMS(e2, m2, ab + 256);

        P1CHUNK(e0, m0);
        P1CHUNK(e1, m1);
        P1CHUNK(e2, m2);
        // rare fallback (arbitrary masks): continue scan+exp over chunks 3..15
        if (beta * T < 106.f) {
            for (int i = 3; i < 16 && beta * T < 106.f; i++) {
                const float4 e = evr[lane + 32 * i];
                const float4 m = mkr[lane + 32 * i];
                P1CHUNK(e, m);
            }
        }
    } else if (q == 1) {
        // ---- chunks 3..6 ----
        const float4 e0 = evr[lane + 32*3], e1 = evr[lane + 32*4];
        const float4 e2 = evr[lane + 32*5], e3 = evr[lane + 32*6];
        const float4 m0 = mkr[lane + 32*3], m1 = mkr[lane + 32*4];
        const float4 m2 = mkr[lane + 32*5], m3 = mkr[lane + 32*6];
        const int ab = 4 * lane;
        SUMS(e0, m0, ab + 384); SUMS(e1, m1, ab + 512);
        SUMS(e2, m2, ab + 640); SUMS(e3, m3, ab + 768);
    } else if (q == 2) {
        // ---- chunks 7..10 ----
        const float4 e0 = evr[lane + 32*7], e1 = evr[lane + 32*8];
        const float4 e2 = evr[lane + 32*9], e3 = evr[lane + 32*10];
        const float4 m0 = mkr[lane + 32*7], m1 = mkr[lane + 32*8];
        const float4 m2 = mkr[lane + 32*9], m3 = mkr[lane + 32*10];
        const int ab = 4 * lane;
        SUMS(e0, m0, ab +  896); SUMS(e1, m1, ab + 1024);
        SUMS(e2, m2, ab + 1152); SUMS(e3, m3, ab + 1280);
    } else {
        // ---- chunks 11..15 ----
        const float4 e0 = evr[lane + 32*11], e1 = evr[lane + 32*12];
        const float4 e2 = evr[lane + 32*13], e3 = evr[lane + 32*14];
        const float4 e4 = evr[lane + 32*15];
        const float4 m0 = mkr[lane + 32*11], m1 = mkr[lane + 32*12];
        const float4 m2 = mkr[lane + 32*13], m3 = mkr[lane + 32*14];
        const float4 m4 = mkr[lane + 32*15];
        const int ab = 4 * lane;
        SUMS(e0, m0, ab + 1408); SUMS(e1, m1, ab + 1536);
        SUMS(e2, m2, ab + 1664); SUMS(e3, m3, ab + 1792);
        SUMS(e4, m4, ab + 1920);
    }

    // ---- warp reductions ----
    #pragma unroll
    for (int off = 16; off; off >>= 1) {
        sumt   += __shfl_down_sync(FULL, sumt,   off);
        sumidx += __shfl_down_sync(FULL, sumidx, off);
        S      += __shfl_down_sync(FULL, S,      off);
    }

    if (lane == 0) {
        sm[w][0] = sumt;
        sm[w][1] = sumidx;
        sm[w][2] = S;
        sm[w][3] = T;
    }
    __syncthreads();

    if (q == 0 && lane == 0) {
        // my row's quarters are warps w .. w+3
        const float st = (sm[w][0] + sm[w+1][0]) + (sm[w+2][0] + sm[w+3][0]);
        const float si = (sm[w][1] + sm[w+1][1]) + (sm[w+2][1] + sm[w+3][1]);
        const float Ss = sm[w][2];     // only q==0 produced S, T
        const float Tt = sm[w][3];

        const float ll  = fmaf(mu, st, -beta * si);
        const float emb = expf(-beta);
        // telescoped compensator: (1-e^{-b})*S - e^{mu*t0} + e^{mu*t1 - b*M}
        float comp = fmaf(1.f - emb, Ss, -expf(mu * t0));
        comp += expf(fmaf(mu, t1, -beta * Tt));   // exact 0 after underflow
        out[row] = ll - comp / mu;
    }
}

extern "C" void kernel_launch(void* const* d_in, const int* in_sizes, int n_in,
                              void* d_out, int out_size)
{
    const float* event_times = (const float*)d_in[0];
    // d_in[1] = spatial_locations : unused by the op
    const float* input_mask  = (const float*)d_in[2];
    const float* t0          = (const float*)d_in[3];
    const float* t1          = (const float*)d_in[4];
    const float* mu_param    = (const float*)d_in[5];
    const float* beta_param  = (const float*)d_in[6];
    float* out = (float*)d_out;

    const int n_units  = NROWS * 4;            // 32768 quarter-row units
    const int n_blocks = n_units / WPB;        // 4096
    scpp_kernel<<<n_blocks, 256>>>(event_times, input_mask,
                                   t0, t1, mu_param, beta_param, out);
}